// round 3
// baseline (speedup 1.0000x reference)
#include <cuda_runtime.h>
#include <cuda_bf16.h>
#include <cstdint>

#define N_NODES 100000
#define N_EDGES 1600000
#define D 128

// ---------------- device scratch (no cudaMalloc allowed) ----------------
__device__ int   g_deg[N_NODES];
__device__ int   g_off[N_NODES + 1];
__device__ int   g_cur[N_NODES];
__device__ int   g_csr[N_EDGES];
__device__ int   g_is_i32;      // 1 if edge_index buffer is int32, 0 if int64
__device__ float g_agg[(size_t)N_NODES * D];
__device__ float g_h  [(size_t)N_NODES * D];

// ---------------- dtype detection + CSR build ----------------
__global__ void zero_deg_kernel() {
    int i = blockIdx.x * blockDim.x + threadIdx.x;
    if (i < N_NODES) g_deg[i] = 0;
    if (i == 0) g_is_i32 = 0;
}

// Interpret first N_EDGES 64-bit slots (= 12.8MB, safe under either dtype).
// True int64 data: every value is a node id < N_NODES. Int32 data: slots pack
// two ids; value >= 2^32 whenever high id > 0 -> flag int32.
__global__ void detect_dtype_kernel(const unsigned long long* __restrict__ ei) {
    int e = blockIdx.x * blockDim.x + threadIdx.x;
    if (e < N_EDGES) {
        if (ei[e] >= (unsigned long long)N_NODES) atomicOr(&g_is_i32, 1);
    }
}

__device__ __forceinline__ void load_edge(const void* ei, int e, int is32,
                                          int& s, int& d) {
    if (is32) {
        const int* p = (const int*)ei;
        s = p[e];
        d = p[N_EDGES + e];
    } else {
        const long long* p = (const long long*)ei;
        s = (int)p[e];
        d = (int)p[N_EDGES + e];
    }
}

__global__ void hist_kernel(const void* __restrict__ ei) {
    int e = blockIdx.x * blockDim.x + threadIdx.x;
    if (e < N_EDGES) {
        int s, d;
        load_edge(ei, e, g_is_i32, s, d);
        if ((unsigned)d < (unsigned)N_NODES) atomicAdd(&g_deg[d], 1);
    }
}

// single-block exclusive scan of g_deg -> g_off, g_cur
__global__ void scan_kernel() {
    __shared__ int s[1024];
    const int CHUNK = (N_NODES + 1023) / 1024;   // 98
    int t = threadIdx.x;
    int start = t * CHUNK;
    int end = start + CHUNK; if (end > N_NODES) end = N_NODES;
    if (start > N_NODES) start = N_NODES;
    int sum = 0;
    for (int i = start; i < end; i++) sum += g_deg[i];
    s[t] = sum;
    __syncthreads();
    for (int d = 1; d < 1024; d <<= 1) {
        int v = 0;
        if (t >= d) v = s[t - d];
        __syncthreads();
        s[t] += v;
        __syncthreads();
    }
    int run = (t > 0) ? s[t - 1] : 0;
    for (int i = start; i < end; i++) {
        g_off[i] = run;
        g_cur[i] = run;
        run += g_deg[i];
    }
    if (t == 1023) g_off[N_NODES] = s[1023];
}

__global__ void fill_kernel(const void* __restrict__ ei) {
    int e = blockIdx.x * blockDim.x + threadIdx.x;
    if (e < N_EDGES) {
        int s, d;
        load_edge(ei, e, g_is_i32, s, d);
        if ((unsigned)d < (unsigned)N_NODES && (unsigned)s < (unsigned)N_NODES) {
            int p = atomicAdd(&g_cur[d], 1);
            g_csr[p] = s;
        }
    }
}

// ---------------- aggregation: warp per node, mean of neighbor rows ----------
__global__ void agg_kernel(const float* __restrict__ x, int use_h) {
    int gw = (blockIdx.x * blockDim.x + threadIdx.x) >> 5;
    int lane = threadIdx.x & 31;
    if (gw >= N_NODES) return;
    const float* feat = use_h ? (const float*)g_h : x;
    int b = g_off[gw];
    int e = g_off[gw + 1];
    float4 acc = make_float4(0.f, 0.f, 0.f, 0.f);
    for (int j = b; j < e; j++) {
        int sN = g_csr[j];
        float4 v = *(const float4*)(feat + (size_t)sN * D + lane * 4);
        acc.x += v.x; acc.y += v.y; acc.z += v.z; acc.w += v.w;
    }
    int cnt = e - b;
    float inv = 1.0f / (float)(cnt > 0 ? cnt : 1);
    acc.x *= inv; acc.y *= inv; acc.z *= inv; acc.w *= inv;
    *(float4*)(g_agg + (size_t)gw * D + lane * 4) = acc;
}

// ---------------- fused dual GEMM: out = g_agg@Wl + self@Wr + b (opt. relu) --
// 128 nodes x 128 cols per block, 256 threads, 8x8 per thread.
__global__ __launch_bounds__(256, 2) void gemm_kernel(
    const float* __restrict__ x,
    const float* __restrict__ Wl,
    const float* __restrict__ Wr,
    const float* __restrict__ bias,
    float* __restrict__ out,
    int self_from_h, int out_to_h, int do_relu)
{
    __shared__ float sA[128][36];
    __shared__ float sW[32][128];

    int tid = threadIdx.x;
    int r = tid >> 4;
    int c = tid & 15;
    int node0 = blockIdx.x * 128;

    const float* A1 = self_from_h ? (const float*)g_h : x;
    float* dst = out_to_h ? (float*)g_h : out;

    float acc[8][8];
#pragma unroll
    for (int i = 0; i < 8; i++)
#pragma unroll
        for (int j = 0; j < 8; j++) acc[i][j] = 0.f;

    for (int kc = 0; kc < 256; kc += 32) {
        const float* Wsrc = (kc < 128) ? (Wl + kc * D) : (Wr + (kc - 128) * D);
        const float* Asrc = (kc < 128) ? (const float*)g_agg : A1;
        int kbase = (kc < 128) ? kc : (kc - 128);

#pragma unroll
        for (int i = 0; i < 4; i++) {
            int idx = tid + i * 256;
            int kk = idx >> 5;
            int c4 = idx & 31;
            float4 v = *(const float4*)(Wsrc + kk * D + c4 * 4);
            *(float4*)(&sW[kk][c4 * 4]) = v;
        }
#pragma unroll
        for (int i = 0; i < 4; i++) {
            int idx = tid + i * 256;
            int n = idx >> 3;
            int k4 = idx & 7;
            int node = node0 + n;
            float4 v = make_float4(0.f, 0.f, 0.f, 0.f);
            if (node < N_NODES)
                v = *(const float4*)(Asrc + (size_t)node * D + kbase + k4 * 4);
            *(float4*)(&sA[n][k4 * 4]) = v;
        }
        __syncthreads();

#pragma unroll 8
        for (int k = 0; k < 32; k++) {
            float wv[8];
#pragma unroll
            for (int j = 0; j < 8; j++) wv[j] = sW[k][c * 8 + j];
            float av[8];
#pragma unroll
            for (int i = 0; i < 8; i++) av[i] = sA[r * 8 + i][k];
#pragma unroll
            for (int i = 0; i < 8; i++)
#pragma unroll
                for (int j = 0; j < 8; j++)
                    acc[i][j] = fmaf(av[i], wv[j], acc[i][j]);
        }
        __syncthreads();
    }

#pragma unroll
    for (int i = 0; i < 8; i++) {
        int node = node0 + r * 8 + i;
        if (node >= N_NODES) continue;
#pragma unroll
        for (int j = 0; j < 8; j++) {
            int col = c * 8 + j;
            float v = acc[i][j] + bias[col];
            if (do_relu) v = fmaxf(v, 0.f);
            dst[(size_t)node * D + col] = v;
        }
    }
}

// ---------------- launch ----------------
extern "C" void kernel_launch(void* const* d_in, const int* in_sizes, int n_in,
                              void* d_out, int out_size) {
    const float* x   = (const float*)d_in[0];
    const void*  ei  = d_in[1];
    const float* Wl1 = (const float*)d_in[2];
    const float* b1  = (const float*)d_in[3];
    const float* Wr1 = (const float*)d_in[4];
    const float* Wl2 = (const float*)d_in[5];
    const float* b2  = (const float*)d_in[6];
    const float* Wr2 = (const float*)d_in[7];
    float* out = (float*)d_out;

    zero_deg_kernel<<<(N_NODES + 255) / 256, 256>>>();
    detect_dtype_kernel<<<(N_EDGES + 255) / 256, 256>>>(
        (const unsigned long long*)ei);
    hist_kernel<<<(N_EDGES + 255) / 256, 256>>>(ei);
    scan_kernel<<<1, 1024>>>();
    fill_kernel<<<(N_EDGES + 255) / 256, 256>>>(ei);

    // layer 1: agg(x) -> g_agg ; g_h = relu(g_agg@Wl1 + b1 + x@Wr1)
    agg_kernel<<<(N_NODES * 32 + 255) / 256, 256>>>(x, 0);
    gemm_kernel<<<(N_NODES + 127) / 128, 256>>>(x, Wl1, Wr1, b1, out, 0, 1, 1);

    // layer 2: agg(g_h) -> g_agg ; out = g_agg@Wl2 + b2 + g_h@Wr2
    agg_kernel<<<(N_NODES * 32 + 255) / 256, 256>>>(x, 1);
    gemm_kernel<<<(N_NODES + 127) / 128, 256>>>(x, Wl2, Wr2, b2, out, 1, 0, 0);
}